// round 1
// baseline (speedup 1.0000x reference)
#include <cuda_runtime.h>
#include <math.h>

#define BB 8
#define CC 64
#define HH 64
#define WW 64

// ---------------- scratch (static device globals; no allocation) ----------------
__device__ float g_feat[BB*CC*HH*WW];      // [B][C][H][W]
__device__ float g_f1[BB*4096*CC];         // [B][N][C] pooled/transposed features
__device__ float g_f2[BB*1024*CC];
__device__ float g_f4[BB*256*CC];
__device__ float g_o1[BB*CC*4096];         // [B][C][h'][w'] attention outputs
__device__ float g_o2[BB*CC*1024];
__device__ float g_o4[BB*CC*256];

// ---------------- Stage 1: 3x3 conv + depthwise Laplacian ----------------
// grid (16 tiles, B), 256 threads; each thread = 1 output pixel, 64 oc accumulators.
__global__ void __launch_bounds__(256) conv_kernel(const float* __restrict__ x,
                                                   const float* __restrict__ w) {
    __shared__ float xs[18][18];
    __shared__ float ws[64][9];
    const int tile = blockIdx.x;
    const int b = blockIdx.y;
    const int y0 = (tile >> 2) << 4;
    const int x0 = (tile & 3) << 4;
    const int tid = threadIdx.x;
    const int px = tid & 15, py = tid >> 4;
    float acc[64];
#pragma unroll
    for (int i = 0; i < 64; i++) acc[i] = 0.f;
    const float* xb = x + b*CC*HH*WW;
    for (int ic = 0; ic < 64; ic++) {
        for (int i = tid; i < 18*18; i += 256) {
            int yy = i / 18, xx = i % 18;
            int gy = y0 + yy - 1, gx = x0 + xx - 1;
            float v = 0.f;
            if (gy >= 0 && gy < HH && gx >= 0 && gx < WW)
                v = xb[ic*HH*WW + gy*WW + gx];
            xs[yy][xx] = v;
        }
        for (int i = tid; i < 576; i += 256) {
            int oc = i / 9, k = i % 9;
            ws[oc][k] = w[oc*576 + ic*9 + k];
        }
        __syncthreads();
        float xv[9];
#pragma unroll
        for (int dy = 0; dy < 3; dy++)
#pragma unroll
            for (int dx = 0; dx < 3; dx++)
                xv[dy*3+dx] = xs[py+dy][px+dx];
        // Laplacian [[0,1,0],[1,-4,1],[0,1,0]] on channel ic
        float lap = xv[1] + xv[3] + xv[5] + xv[7] - 4.f*xv[4];
#pragma unroll
        for (int oc = 0; oc < 64; oc++) {
            float a = acc[oc];
#pragma unroll
            for (int k = 0; k < 9; k++) a = fmaf(xv[k], ws[oc][k], a);
            acc[oc] = a + ((oc == ic) ? lap : 0.f);
        }
        __syncthreads();
    }
    float* fb = g_feat + b*CC*HH*WW + (y0+py)*WW + x0 + px;
#pragma unroll
    for (int oc = 0; oc < 64; oc++)
        fb[oc*HH*WW] = acc[oc];
}

// ---------------- Stage 2a: pool (exact s x s mean) + transpose to [B][N][C] ----------------
template<int S>
__global__ void __launch_bounds__(256) pool_kernel() {
    constexpr int WP = WW / S;
    constexpr int N  = (HH/S) * (WW/S);
    float* out = (S == 1) ? g_f1 : (S == 2) ? g_f2 : g_f4;
    __shared__ float tile[32][33];
    const int b  = blockIdx.z;
    const int c0 = blockIdx.y * 32;
    const int n0 = blockIdx.x * 32;
    const int tid = threadIdx.x;
    const int tx = tid & 31, ty = tid >> 5;
    for (int ci = ty; ci < 32; ci += 8) {
        int n = n0 + tx;
        int ny = n / WP, nx = n % WP;
        const float* fp = g_feat + ((b*CC + c0 + ci)*HH + ny*S)*WW + nx*S;
        float s = 0.f;
#pragma unroll
        for (int dy = 0; dy < S; dy++)
#pragma unroll
            for (int dx = 0; dx < S; dx++)
                s += fp[dy*WW + dx];
        tile[ci][tx] = s * (1.f/(S*S));
    }
    __syncthreads();
    for (int ni = ty; ni < 32; ni += 8)
        out[(b*N + n0 + ni)*CC + c0 + tx] = tile[tx][ni];
}

// ---------------- Stage 2b: flash non-local attention (Q=K=V=f) ----------------
#define GEMM16(acc, a, b) \
    acc[0][0] = fmaf(a.x, b.x, acc[0][0]); \
    acc[0][1] = fmaf(a.x, b.y, acc[0][1]); \
    acc[0][2] = fmaf(a.x, b.z, acc[0][2]); \
    acc[0][3] = fmaf(a.x, b.w, acc[0][3]); \
    acc[1][0] = fmaf(a.y, b.x, acc[1][0]); \
    acc[1][1] = fmaf(a.y, b.y, acc[1][1]); \
    acc[1][2] = fmaf(a.y, b.z, acc[1][2]); \
    acc[1][3] = fmaf(a.y, b.w, acc[1][3]); \
    acc[2][0] = fmaf(a.z, b.x, acc[2][0]); \
    acc[2][1] = fmaf(a.z, b.y, acc[2][1]); \
    acc[2][2] = fmaf(a.z, b.z, acc[2][2]); \
    acc[2][3] = fmaf(a.z, b.w, acc[2][3]); \
    acc[3][0] = fmaf(a.w, b.x, acc[3][0]); \
    acc[3][1] = fmaf(a.w, b.y, acc[3][1]); \
    acc[3][2] = fmaf(a.w, b.z, acc[3][2]); \
    acc[3][3] = fmaf(a.w, b.w, acc[3][3]);

// 256 threads (16x16). BM=64 queries, BN=64 keys per iteration. 4x4 register tiles.
// smem (dynamic, 64KB): Qt[c][r], Kt[c][k] (channel-major for S-gemm),
//                       Ks[k][c] (row-major = V for PV-gemm), Pt[k][r].
template<int N>
__global__ void __launch_bounds__(256) attn_kernel() {
    const float* f = (N == 4096) ? g_f1 : (N == 1024) ? g_f2 : g_f4;
    float* outp    = (N == 4096) ? g_o1 : (N == 1024) ? g_o2 : g_o4;
    extern __shared__ float smem[];
    float (*Qt)[64] = (float(*)[64])(smem);
    float (*Kt)[64] = (float(*)[64])(smem + 4096);
    float (*Ks)[64] = (float(*)[64])(smem + 8192);
    float (*Pt)[64] = (float(*)[64])(smem + 12288);

    const int b   = blockIdx.y;
    const int q0  = blockIdx.x * 64;
    const int tid = threadIdx.x;
    const int tx  = tid & 15, ty = tid >> 4;
    const float* fb = f + b * N * 64;

    // load Q tile (transposed into channel-major)
#pragma unroll
    for (int it = 0; it < 4; it++) {
        int lin = (tid + it*256) * 4;
        int r = lin >> 6, c0 = lin & 63;
        float4 v = *(const float4*)(fb + (q0 + r)*64 + c0);
        Qt[c0+0][r] = v.x; Qt[c0+1][r] = v.y; Qt[c0+2][r] = v.z; Qt[c0+3][r] = v.w;
    }

    float m_i[4], l_i[4], o[4][4];
#pragma unroll
    for (int i = 0; i < 4; i++) {
        m_i[i] = -1e30f; l_i[i] = 0.f;
#pragma unroll
        for (int j = 0; j < 4; j++) o[i][j] = 0.f;
    }

    for (int kb = 0; kb < N/64; kb++) {
        // load K tile once, store both layouts (K for S-gemm, V for PV-gemm)
#pragma unroll
        for (int it = 0; it < 4; it++) {
            int lin = (tid + it*256) * 4;
            int r = lin >> 6, c0 = lin & 63;
            float4 v = *(const float4*)(fb + (kb*64 + r)*64 + c0);
            *(float4*)&Ks[r][c0] = v;
            Kt[c0+0][r] = v.x; Kt[c0+1][r] = v.y; Kt[c0+2][r] = v.z; Kt[c0+3][r] = v.w;
        }
        __syncthreads();                                     // (A)

        // S = Q K^T
        float s[4][4];
#pragma unroll
        for (int i = 0; i < 4; i++)
#pragma unroll
            for (int j = 0; j < 4; j++) s[i][j] = 0.f;
#pragma unroll 8
        for (int c = 0; c < 64; c++) {
            float4 qv = *(const float4*)&Qt[c][ty*4];
            float4 kv = *(const float4*)&Kt[c][tx*4];
            GEMM16(s, qv, kv)
        }

        // online softmax over the 16 tx-lanes owning each row
#pragma unroll
        for (int i = 0; i < 4; i++) {
            float rmax = fmaxf(fmaxf(s[i][0], s[i][1]), fmaxf(s[i][2], s[i][3]));
            rmax = fmaxf(rmax, __shfl_xor_sync(0xffffffffu, rmax, 1));
            rmax = fmaxf(rmax, __shfl_xor_sync(0xffffffffu, rmax, 2));
            rmax = fmaxf(rmax, __shfl_xor_sync(0xffffffffu, rmax, 4));
            rmax = fmaxf(rmax, __shfl_xor_sync(0xffffffffu, rmax, 8));
            float mnew = fmaxf(m_i[i], rmax);
            float corr = __expf(m_i[i] - mnew);
            m_i[i] = mnew;
            float rsum = 0.f;
#pragma unroll
            for (int j = 0; j < 4; j++) { s[i][j] = __expf(s[i][j] - mnew); rsum += s[i][j]; }
            rsum += __shfl_xor_sync(0xffffffffu, rsum, 1);
            rsum += __shfl_xor_sync(0xffffffffu, rsum, 2);
            rsum += __shfl_xor_sync(0xffffffffu, rsum, 4);
            rsum += __shfl_xor_sync(0xffffffffu, rsum, 8);
            l_i[i] = l_i[i]*corr + rsum;
#pragma unroll
            for (int j = 0; j < 4; j++) o[i][j] *= corr;
        }

        // stage P transposed
#pragma unroll
        for (int j = 0; j < 4; j++)
#pragma unroll
            for (int i = 0; i < 4; i++)
                Pt[tx*4+j][ty*4+i] = s[i][j];
        __syncthreads();                                     // (B)

        // O += P V
#pragma unroll 8
        for (int k = 0; k < 64; k++) {
            float4 pv = *(const float4*)&Pt[k][ty*4];
            float4 vv = *(const float4*)&Ks[k][tx*4];
            GEMM16(o, pv, vv)
        }
        __syncthreads();                                     // (C)
    }

    // epilogue: normalize, stage transposed, write [B][C][N] coalesced
#pragma unroll
    for (int i = 0; i < 4; i++) {
        float inv = 1.f / l_i[i];
#pragma unroll
        for (int j = 0; j < 4; j++)
            Pt[tx*4+j][ty*4+i] = o[i][j] * inv;
    }
    __syncthreads();
    float* ob = outp + b*64*N;
#pragma unroll
    for (int it = 0; it < 4; it++) {
        int lin = (tid + it*256) * 4;
        int d = lin >> 6, r = lin & 63;
        *(float4*)(ob + d*N + q0 + r) = *(const float4*)&Pt[d][r];
    }
}

// ---------------- Stage 3: bilinear upsample (half-pixel, edge clamp) + residual ----------------
__device__ __forceinline__ float bilin(const float* __restrict__ p, int hp,
                                       int y, int x, float inv_s) {
    float sy = (y + 0.5f)*inv_s - 0.5f;
    float sx = (x + 0.5f)*inv_s - 0.5f;
    float fy = floorf(sy), fx = floorf(sx);
    float wy = sy - fy, wx = sx - fx;
    int y0 = max((int)fy, 0), y1 = min((int)fy + 1, hp-1);
    int x0 = max((int)fx, 0), x1 = min((int)fx + 1, hp-1);
    float a = p[y0*hp + x0], b2 = p[y0*hp + x1];
    float c2 = p[y1*hp + x0], d2 = p[y1*hp + x1];
    return (a*(1.f-wx) + b2*wx)*(1.f-wy) + (c2*(1.f-wx) + d2*wx)*wy;
}

__global__ void __launch_bounds__(256) final_kernel(const float* __restrict__ x,
                                                    float* __restrict__ out) {
    int idx = blockIdx.x*256 + threadIdx.x;
    if (idx >= BB*CC*HH*WW) return;
    int xx = idx & 63, yy = (idx >> 6) & 63, bc = idx >> 12;
    float v = x[idx] + g_o1[idx];                 // scale 1: identity resize
    v += bilin(g_o2 + bc*1024, 32, yy, xx, 0.5f); // scale 2
    v += bilin(g_o4 + bc*256,  16, yy, xx, 0.25f);// scale 4
    out[idx] = v;
}

// ---------------- launch ----------------
extern "C" void kernel_launch(void* const* d_in, const int* in_sizes, int n_in,
                              void* d_out, int out_size) {
    const float* x = (const float*)d_in[0];
    const float* w = (const float*)d_in[1];
    float* out = (float*)d_out;

    const int SMEM_ATTN = 64 * 1024;
    cudaFuncSetAttribute(attn_kernel<4096>, cudaFuncAttributeMaxDynamicSharedMemorySize, SMEM_ATTN);
    cudaFuncSetAttribute(attn_kernel<1024>, cudaFuncAttributeMaxDynamicSharedMemorySize, SMEM_ATTN);
    cudaFuncSetAttribute(attn_kernel<256>,  cudaFuncAttributeMaxDynamicSharedMemorySize, SMEM_ATTN);

    conv_kernel<<<dim3(16, 8), 256>>>(x, w);
    pool_kernel<1><<<dim3(128, 2, 8), 256>>>();
    pool_kernel<2><<<dim3(32, 2, 8), 256>>>();
    pool_kernel<4><<<dim3(8, 2, 8), 256>>>();
    attn_kernel<4096><<<dim3(64, 8), 256, SMEM_ATTN>>>();
    attn_kernel<1024><<<dim3(16, 8), 256, SMEM_ATTN>>>();
    attn_kernel<256><<<dim3(4, 8), 256, SMEM_ATTN>>>();
    final_kernel<<<(BB*CC*HH*WW + 255)/256, 256>>>(x, out);
}

// round 3
// speedup vs baseline: 1.8050x; 1.8050x over previous
#include <cuda_runtime.h>
#include <cstdint>
#include <math.h>

#define BB 8
#define CC 64
#define HH 64
#define WW 64

// ---------------- scratch (static device globals; no allocation) ----------------
__device__ float g_feat[BB*CC*HH*WW];      // [B][C][H][W]
__device__ float g_f1[BB*4096*CC];         // [B][N][C] pooled/transposed features
__device__ float g_f2[BB*1024*CC];
__device__ float g_f4[BB*256*CC];
__device__ float g_o1[BB*CC*4096];         // [B][C][n] attention outputs
__device__ float g_o2[BB*CC*1024];
__device__ float g_o4[BB*CC*256];

__device__ __forceinline__ float tf32r(float v) {   // round-to-nearest tf32
    uint32_t u;
    asm("cvt.rna.tf32.f32 %0, %1;" : "=r"(u) : "f"(v));
    return __uint_as_float(u);
}

// m16n8k8 tf32 MMA, row.col, fp32 accumulate-in-place
__device__ __forceinline__ void mma8(float* d, const uint32_t* a, uint32_t b0, uint32_t b1) {
    asm volatile("mma.sync.aligned.m16n8k8.row.col.f32.tf32.tf32.f32 "
        "{%0,%1,%2,%3}, {%4,%5,%6,%7}, {%8,%9}, {%0,%1,%2,%3};"
        : "+f"(d[0]), "+f"(d[1]), "+f"(d[2]), "+f"(d[3])
        : "r"(a[0]), "r"(a[1]), "r"(a[2]), "r"(a[3]), "r"(b0), "r"(b1));
}

// ---------------- Stage 1: 3x3 conv + depthwise Laplacian ----------------
__global__ void __launch_bounds__(256) conv_kernel(const float* __restrict__ x,
                                                   const float* __restrict__ w) {
    __shared__ float xs[18][18];
    __shared__ float ws[64][9];
    const int tile = blockIdx.x;
    const int b = blockIdx.y;
    const int y0 = (tile >> 2) << 4;
    const int x0 = (tile & 3) << 4;
    const int tid = threadIdx.x;
    const int px = tid & 15, py = tid >> 4;
    float acc[64];
#pragma unroll
    for (int i = 0; i < 64; i++) acc[i] = 0.f;
    const float* xb = x + b*CC*HH*WW;
    for (int ic = 0; ic < 64; ic++) {
        for (int i = tid; i < 18*18; i += 256) {
            int yy = i / 18, xx = i % 18;
            int gy = y0 + yy - 1, gx = x0 + xx - 1;
            float v = 0.f;
            if (gy >= 0 && gy < HH && gx >= 0 && gx < WW)
                v = xb[ic*HH*WW + gy*WW + gx];
            xs[yy][xx] = v;
        }
        for (int i = tid; i < 576; i += 256) {
            int oc = i / 9, k = i % 9;
            ws[oc][k] = w[oc*576 + ic*9 + k];
        }
        __syncthreads();
        float xv[9];
#pragma unroll
        for (int dy = 0; dy < 3; dy++)
#pragma unroll
            for (int dx = 0; dx < 3; dx++)
                xv[dy*3+dx] = xs[py+dy][px+dx];
        float lap = xv[1] + xv[3] + xv[5] + xv[7] - 4.f*xv[4];
#pragma unroll
        for (int oc = 0; oc < 64; oc++) {
            float a = acc[oc];
#pragma unroll
            for (int k = 0; k < 9; k++) a = fmaf(xv[k], ws[oc][k], a);
            acc[oc] = a + ((oc == ic) ? lap : 0.f);
        }
        __syncthreads();
    }
    float* fb = g_feat + b*CC*HH*WW + (y0+py)*WW + x0 + px;
#pragma unroll
    for (int oc = 0; oc < 64; oc++)
        fb[oc*HH*WW] = acc[oc];
}

// ---------------- Stage 2a: pool + transpose to [B][N][C] ----------------
template<int S>
__global__ void __launch_bounds__(256) pool_kernel() {
    constexpr int WP = WW / S;
    constexpr int N  = (HH/S) * (WW/S);
    float* out = (S == 1) ? g_f1 : (S == 2) ? g_f2 : g_f4;
    __shared__ float tile[32][33];
    const int b  = blockIdx.z;
    const int c0 = blockIdx.y * 32;
    const int n0 = blockIdx.x * 32;
    const int tid = threadIdx.x;
    const int tx = tid & 31, ty = tid >> 5;
    for (int ci = ty; ci < 32; ci += 8) {
        int n = n0 + tx;
        int ny = n / WP, nx = n % WP;
        const float* fp = g_feat + ((b*CC + c0 + ci)*HH + ny*S)*WW + nx*S;
        float s = 0.f;
#pragma unroll
        for (int dy = 0; dy < S; dy++)
#pragma unroll
            for (int dx = 0; dx < S; dx++)
                s += fp[dy*WW + dx];
        tile[ci][tx] = s * (1.f/(S*S));
    }
    __syncthreads();
    for (int ni = ty; ni < 32; ni += 8)
        out[(b*N + n0 + ni)*CC + c0 + tx] = tile[tx][ni];
}

// ---------------- Stage 2b: mma.sync tf32 flash attention ----------------
// CTA: 64 queries, 128 threads (4 warps), 64-key tiles.
// Warp w owns q-rows [16w, 16w+16). Softmax + P are warp-local.
// smem tiles: stride 68 floats (conflict-free fragment LDS).
//   QH/QL [64][68] split-tf32 Q; KH/KL [64][68] split-tf32 K;
//   VT [64ch][68] = tf32(V) transposed; PT [64][68] tf32 P.
#define TSTR 68
#define TSZ  (64*TSTR)
#define ATTN_SMEM (6*TSZ*4)

template<int N>
__global__ void __launch_bounds__(128, 2) attn_mma() {
    const float* f = (N == 4096) ? g_f1 : (N == 1024) ? g_f2 : g_f4;
    float* outp    = (N == 4096) ? g_o1 : (N == 1024) ? g_o2 : g_o4;
    extern __shared__ float sm[];
    float* QH = sm;
    float* QL = sm + TSZ;
    float* KH = sm + 2*TSZ;
    float* KL = sm + 3*TSZ;
    float* VT = sm + 4*TSZ;
    float* PT = sm + 5*TSZ;

    const int tid  = threadIdx.x;
    const int w    = tid >> 5;
    const int lane = tid & 31;
    const int g    = lane >> 2;      // group id (row within fragment)
    const int q4   = lane & 3;       // thread-in-group
    const int b    = blockIdx.y;
    const int q0   = blockIdx.x * 64;
    const float* fb = f + (size_t)b * N * 64;
    const int r0 = w*16 + g;         // this thread's first local q-row

    // ---- load Q tile (split hi/lo) ----
    {
        int row = tid >> 1, half = tid & 1;
        const float4* src = (const float4*)(fb + (size_t)(q0 + row)*64 + half*32);
#pragma unroll
        for (int i = 0; i < 8; i++) {
            float4 v = src[i];
            float hx = tf32r(v.x), hy = tf32r(v.y), hz = tf32r(v.z), hw = tf32r(v.w);
            int c = half*32 + i*4;
            float* qh = QH + row*TSTR + c;
            float* ql = QL + row*TSTR + c;
            qh[0]=hx; qh[1]=hy; qh[2]=hz; qh[3]=hw;
            ql[0]=v.x-hx; ql[1]=v.y-hy; ql[2]=v.z-hz; ql[3]=v.w-hw;
        }
    }

    float m0 = -3.0e38f, m1 = -3.0e38f, l0 = 0.f, l1 = 0.f;
    float o[8][4];
#pragma unroll
    for (int nb = 0; nb < 8; nb++)
#pragma unroll
        for (int j = 0; j < 4; j++) o[nb][j] = 0.f;

    for (int kb = 0; kb < N/64; kb++) {
        __syncthreads();   // prior-iteration smem reads done (also publishes Q on kb=0)
        // ---- load K tile: split hi/lo + transposed V (tf32) ----
        {
            int row = tid >> 1, half = tid & 1;
            const float4* src = (const float4*)(fb + (size_t)(kb*64 + row)*64 + half*32);
#pragma unroll
            for (int i = 0; i < 8; i++) {
                float4 v = src[i];
                float hx = tf32r(v.x), hy = tf32r(v.y), hz = tf32r(v.z), hw = tf32r(v.w);
                int c = half*32 + i*4;
                float* kh = KH + row*TSTR + c;
                float* kl = KL + row*TSTR + c;
                kh[0]=hx; kh[1]=hy; kh[2]=hz; kh[3]=hw;
                kl[0]=v.x-hx; kl[1]=v.y-hy; kl[2]=v.z-hz; kl[3]=v.w-hw;
                VT[(c+0)*TSTR + row] = hx;
                VT[(c+1)*TSTR + row] = hy;
                VT[(c+2)*TSTR + row] = hz;
                VT[(c+3)*TSTR + row] = hw;
            }
        }
        __syncthreads();

        // ---- S = Qh*Kh + Qh*Kl + Ql*Kh ----
        float s[8][4];
#pragma unroll
        for (int nb = 0; nb < 8; nb++)
#pragma unroll
            for (int j = 0; j < 4; j++) s[nb][j] = 0.f;

        uint32_t aF[8][4];
#pragma unroll
        for (int ks = 0; ks < 8; ks++) {
            aF[ks][0] = __float_as_uint(QH[ r0     *TSTR + ks*8 + q4    ]);
            aF[ks][1] = __float_as_uint(QH[(r0+8) *TSTR + ks*8 + q4    ]);
            aF[ks][2] = __float_as_uint(QH[ r0     *TSTR + ks*8 + q4 + 4]);
            aF[ks][3] = __float_as_uint(QH[(r0+8) *TSTR + ks*8 + q4 + 4]);
        }
#pragma unroll
        for (int pass = 0; pass < 2; pass++) {
            const float* Kb = pass ? KL : KH;
#pragma unroll
            for (int nb = 0; nb < 8; nb++)
#pragma unroll
                for (int ks = 0; ks < 8; ks++) {
                    uint32_t b0 = __float_as_uint(Kb[(nb*8+g)*TSTR + ks*8 + q4    ]);
                    uint32_t b1 = __float_as_uint(Kb[(nb*8+g)*TSTR + ks*8 + q4 + 4]);
                    mma8(s[nb], aF[ks], b0, b1);
                }
        }
#pragma unroll
        for (int ks = 0; ks < 8; ks++) {
            aF[ks][0] = __float_as_uint(QL[ r0     *TSTR + ks*8 + q4    ]);
            aF[ks][1] = __float_as_uint(QL[(r0+8) *TSTR + ks*8 + q4    ]);
            aF[ks][2] = __float_as_uint(QL[ r0     *TSTR + ks*8 + q4 + 4]);
            aF[ks][3] = __float_as_uint(QL[(r0+8) *TSTR + ks*8 + q4 + 4]);
        }
#pragma unroll
        for (int nb = 0; nb < 8; nb++)
#pragma unroll
            for (int ks = 0; ks < 8; ks++) {
                uint32_t b0 = __float_as_uint(KH[(nb*8+g)*TSTR + ks*8 + q4    ]);
                uint32_t b1 = __float_as_uint(KH[(nb*8+g)*TSTR + ks*8 + q4 + 4]);
                mma8(s[nb], aF[ks], b0, b1);
            }

        // ---- online softmax (rows r0 / r0+8; quad-lane reductions) ----
        float mx0 = -3.0e38f, mx1 = -3.0e38f;
#pragma unroll
        for (int nb = 0; nb < 8; nb++) {
            mx0 = fmaxf(mx0, fmaxf(s[nb][0], s[nb][1]));
            mx1 = fmaxf(mx1, fmaxf(s[nb][2], s[nb][3]));
        }
        mx0 = fmaxf(mx0, __shfl_xor_sync(0xffffffffu, mx0, 1));
        mx0 = fmaxf(mx0, __shfl_xor_sync(0xffffffffu, mx0, 2));
        mx1 = fmaxf(mx1, __shfl_xor_sync(0xffffffffu, mx1, 1));
        mx1 = fmaxf(mx1, __shfl_xor_sync(0xffffffffu, mx1, 2));
        float mn0 = fmaxf(m0, mx0), mn1 = fmaxf(m1, mx1);
        float c0 = __expf(m0 - mn0), c1 = __expf(m1 - mn1);
        m0 = mn0; m1 = mn1;
        float sum0 = 0.f, sum1 = 0.f;
#pragma unroll
        for (int nb = 0; nb < 8; nb++) {
            s[nb][0] = __expf(s[nb][0] - mn0); sum0 += s[nb][0];
            s[nb][1] = __expf(s[nb][1] - mn0); sum0 += s[nb][1];
            s[nb][2] = __expf(s[nb][2] - mn1); sum1 += s[nb][2];
            s[nb][3] = __expf(s[nb][3] - mn1); sum1 += s[nb][3];
        }
        sum0 += __shfl_xor_sync(0xffffffffu, sum0, 1);
        sum0 += __shfl_xor_sync(0xffffffffu, sum0, 2);
        sum1 += __shfl_xor_sync(0xffffffffu, sum1, 1);
        sum1 += __shfl_xor_sync(0xffffffffu, sum1, 2);
        l0 = l0*c0 + sum0;
        l1 = l1*c1 + sum1;
#pragma unroll
        for (int nb = 0; nb < 8; nb++) {
            o[nb][0] *= c0; o[nb][1] *= c0;
            o[nb][2] *= c1; o[nb][3] *= c1;
        }

        // ---- stage P (tf32) — warp-private rows, only __syncwarp needed ----
#pragma unroll
        for (int nb = 0; nb < 8; nb++) {
            int col = nb*8 + 2*q4;
            PT[ r0    *TSTR + col    ] = tf32r(s[nb][0]);
            PT[ r0    *TSTR + col + 1] = tf32r(s[nb][1]);
            PT[(r0+8) *TSTR + col    ] = tf32r(s[nb][2]);
            PT[(r0+8) *TSTR + col + 1] = tf32r(s[nb][3]);
        }
        __syncwarp();

        // ---- O += P @ V ----
#pragma unroll
        for (int ks = 0; ks < 8; ks++) {
            aF[ks][0] = __float_as_uint(PT[ r0     *TSTR + ks*8 + q4    ]);
            aF[ks][1] = __float_as_uint(PT[(r0+8) *TSTR + ks*8 + q4    ]);
            aF[ks][2] = __float_as_uint(PT[ r0     *TSTR + ks*8 + q4 + 4]);
            aF[ks][3] = __float_as_uint(PT[(r0+8) *TSTR + ks*8 + q4 + 4]);
        }
#pragma unroll
        for (int nb = 0; nb < 8; nb++)
#pragma unroll
            for (int ks = 0; ks < 8; ks++) {
                uint32_t b0 = __float_as_uint(VT[(nb*8+g)*TSTR + ks*8 + q4    ]);
                uint32_t b1 = __float_as_uint(VT[(nb*8+g)*TSTR + ks*8 + q4 + 4]);
                mma8(o[nb], aF[ks], b0, b1);
            }
    }

    // ---- epilogue: normalize, write [B][C][N] ----
    float i0 = 1.f / l0, i1 = 1.f / l1;
    float* ob = outp + (size_t)b * 64 * N;
#pragma unroll
    for (int nb = 0; nb < 8; nb++) {
        int c = nb*8 + 2*q4;
        ob[(size_t) c   *N + q0 + r0    ] = o[nb][0]*i0;
        ob[(size_t)(c+1)*N + q0 + r0    ] = o[nb][1]*i0;
        ob[(size_t) c   *N + q0 + r0 + 8] = o[nb][2]*i1;
        ob[(size_t)(c+1)*N + q0 + r0 + 8] = o[nb][3]*i1;
    }
}

// ---------------- Stage 3: bilinear upsample + residual ----------------
__device__ __forceinline__ float bilin(const float* __restrict__ p, int hp,
                                       int y, int x, float inv_s) {
    float sy = (y + 0.5f)*inv_s - 0.5f;
    float sx = (x + 0.5f)*inv_s - 0.5f;
    float fy = floorf(sy), fx = floorf(sx);
    float wy = sy - fy, wx = sx - fx;
    int y0 = max((int)fy, 0), y1 = min((int)fy + 1, hp-1);
    int x0 = max((int)fx, 0), x1 = min((int)fx + 1, hp-1);
    float a = p[y0*hp + x0], b2 = p[y0*hp + x1];
    float c2 = p[y1*hp + x0], d2 = p[y1*hp + x1];
    return (a*(1.f-wx) + b2*wx)*(1.f-wy) + (c2*(1.f-wx) + d2*wx)*wy;
}

__global__ void __launch_bounds__(256) final_kernel(const float* __restrict__ x,
                                                    float* __restrict__ out) {
    int idx = blockIdx.x*256 + threadIdx.x;
    if (idx >= BB*CC*HH*WW) return;
    int xx = idx & 63, yy = (idx >> 6) & 63, bc = idx >> 12;
    float v = x[idx] + g_o1[idx];
    v += bilin(g_o2 + bc*1024, 32, yy, xx, 0.5f);
    v += bilin(g_o4 + bc*256,  16, yy, xx, 0.25f);
    out[idx] = v;
}

// ---------------- launch ----------------
extern "C" void kernel_launch(void* const* d_in, const int* in_sizes, int n_in,
                              void* d_out, int out_size) {
    const float* x = (const float*)d_in[0];
    const float* w = (const float*)d_in[1];
    float* out = (float*)d_out;

    cudaFuncSetAttribute(attn_mma<4096>, cudaFuncAttributeMaxDynamicSharedMemorySize, ATTN_SMEM);
    cudaFuncSetAttribute(attn_mma<1024>, cudaFuncAttributeMaxDynamicSharedMemorySize, ATTN_SMEM);
    cudaFuncSetAttribute(attn_mma<256>,  cudaFuncAttributeMaxDynamicSharedMemorySize, ATTN_SMEM);

    conv_kernel<<<dim3(16, 8), 256>>>(x, w);
    pool_kernel<1><<<dim3(128, 2, 8), 256>>>();
    pool_kernel<2><<<dim3(32, 2, 8), 256>>>();
    pool_kernel<4><<<dim3(8, 2, 8), 256>>>();
    attn_mma<4096><<<dim3(64, 8), 128, ATTN_SMEM>>>();
    attn_mma<1024><<<dim3(16, 8), 128, ATTN_SMEM>>>();
    attn_mma<256> <<<dim3(4, 8),  128, ATTN_SMEM>>>();
    final_kernel<<<(BB*CC*HH*WW + 255)/256, 256>>>(x, out);
}